// round 1
// baseline (speedup 1.0000x reference)
#include <cuda_runtime.h>
#include <math.h>

// Problem constants
#define NB   4
#define NT   512
#define NH   512
#define NV   32000
#define NS   512
#define NSDV 300
#define NTDV 512
#define MM   (NB*NT)              // 2048 rows
#define NOUT (NV+NSDV+NTDV)       // 32812

// Scratch (static device arrays; no allocation allowed)
__device__ float g_scores[(size_t)MM*NV];   // 262 MB
__device__ float g_p[MM*3];
__device__ int   g_src_idx[NB*NS];
__device__ int   g_tgt_idx[NB*NT];

// ---------------------------------------------------------------------------
// Extract one-hot indices from the attention maps (map[b,s,v]==1 at idx[b,s]).
// ---------------------------------------------------------------------------
__global__ void prep_idx_kernel(const float* __restrict__ smap,
                                const float* __restrict__ tmap) {
    int i = blockIdx.x * blockDim.x + threadIdx.x;   // 0..2047
    if (i >= NB*NS) return;
    // source: rows of length NSDV
    {
        const float* r = smap + (size_t)i * NSDV;
        int idx = 0;
        for (int v = 0; v < NSDV; v++) if (r[v] > 0.5f) idx = v;
        g_src_idx[i] = idx;
    }
    // target: rows of length NTDV (n dim == NT == 512 rows total per batch)
    {
        const float* r = tmap + (size_t)i * NTDV;
        int idx = 0;
        for (int v = 0; v < NTDV; v++) if (r[v] > 0.5f) idx = v;
        g_tgt_idx[i] = idx;
    }
}

// ---------------------------------------------------------------------------
// 3-way gate: p = softmax(h @ Wp + bp). One warp per row.
// ---------------------------------------------------------------------------
__global__ void p_kernel(const float* __restrict__ H,
                         const float* __restrict__ Wp,
                         const float* __restrict__ bp) {
    int warp = threadIdx.x >> 5;
    int lane = threadIdx.x & 31;
    int row  = blockIdx.x * 4 + warp;
    if (row >= MM) return;
    const float* h = H + (size_t)row * NH;
    float s0 = 0.f, s1 = 0.f, s2 = 0.f;
    for (int k = lane; k < NH; k += 32) {
        float hv = h[k];
        s0 = fmaf(hv, Wp[k*3+0], s0);
        s1 = fmaf(hv, Wp[k*3+1], s1);
        s2 = fmaf(hv, Wp[k*3+2], s2);
    }
    #pragma unroll
    for (int o = 16; o > 0; o >>= 1) {
        s0 += __shfl_down_sync(0xffffffff, s0, o);
        s1 += __shfl_down_sync(0xffffffff, s1, o);
        s2 += __shfl_down_sync(0xffffffff, s2, o);
    }
    if (lane == 0) {
        s0 += bp[0]; s1 += bp[1]; s2 += bp[2];
        float m = fmaxf(s0, fmaxf(s1, s2));
        float e0 = expf(s0 - m), e1 = expf(s1 - m), e2 = expf(s2 - m);
        float inv = 1.0f / (e0 + e1 + e2);
        g_p[row*3+0] = e0 * inv;
        g_p[row*3+1] = e1 * inv;
        g_p[row*3+2] = e2 * inv;
    }
}

// ---------------------------------------------------------------------------
// SGEMM: g_scores[M, NV] = H[M, NH] @ Wv[NH, NV] + bv
// 128x128 tiles, BK=16, 256 threads, 8x8 per thread.
// ---------------------------------------------------------------------------
__global__ __launch_bounds__(256, 2)
void gemm_kernel(const float* __restrict__ A,
                 const float* __restrict__ B,
                 const float* __restrict__ bias) {
    __shared__ float As[16][132];   // [k][m], padded
    __shared__ float Bs[16][128];   // [k][n]
    const int bn = blockIdx.x * 128;
    const int bm = blockIdx.y * 128;
    const int tid = threadIdx.x;
    const int tm = (tid >> 4) * 8;   // 0..120
    const int tn = (tid & 15) * 8;   // 0..120

    float acc[8][8];
    #pragma unroll
    for (int i = 0; i < 8; i++)
        #pragma unroll
        for (int j = 0; j < 8; j++) acc[i][j] = 0.f;

    for (int k0 = 0; k0 < NH; k0 += 16) {
        // A tile: 128 rows x 16 k, float4 along k
        #pragma unroll
        for (int it = 0; it < 2; it++) {
            int v   = tid + it * 256;        // 0..511
            int row = v >> 2;
            int kc  = (v & 3) * 4;
            float4 a = *(const float4*)&A[(size_t)(bm + row) * NH + k0 + kc];
            As[kc+0][row] = a.x; As[kc+1][row] = a.y;
            As[kc+2][row] = a.z; As[kc+3][row] = a.w;
        }
        // B tile: 16 k x 128 n, float4 along n
        #pragma unroll
        for (int it = 0; it < 2; it++) {
            int v   = tid + it * 256;
            int row = v >> 5;
            int c   = (v & 31) * 4;
            float4 b = *(const float4*)&B[(size_t)(k0 + row) * NV + bn + c];
            *(float4*)&Bs[row][c] = b;
        }
        __syncthreads();
        #pragma unroll
        for (int k = 0; k < 16; k++) {
            float a[8], b[8];
            #pragma unroll
            for (int i = 0; i < 8; i++) a[i] = As[k][tm + i];
            #pragma unroll
            for (int j = 0; j < 8; j++) b[j] = Bs[k][tn + j];
            #pragma unroll
            for (int i = 0; i < 8; i++)
                #pragma unroll
                for (int j = 0; j < 8; j++)
                    acc[i][j] = fmaf(a[i], b[j], acc[i][j]);
        }
        __syncthreads();
    }

    #pragma unroll
    for (int i = 0; i < 8; i++) {
        size_t rowoff = (size_t)(bm + tm + i) * NV + bn + tn;
        #pragma unroll
        for (int j = 0; j < 8; j += 4) {
            float4 o;
            o.x = acc[i][j+0] + bias[bn+tn+j+0];
            o.y = acc[i][j+1] + bias[bn+tn+j+1];
            o.z = acc[i][j+2] + bias[bn+tn+j+2];
            o.w = acc[i][j+3] + bias[bn+tn+j+3];
            *(float4*)&g_scores[rowoff + j] = o;
        }
    }
}

// ---------------------------------------------------------------------------
// Per-row: softmax over V (index 0 masked), scale by p_generate, one-hot
// copy scatters, concat write, fused argmax (+lowest-index tie-break).
// One block (256 threads) per row.
// ---------------------------------------------------------------------------
__global__ __launch_bounds__(256)
void finalize_kernel(const float* __restrict__ satt,
                     const float* __restrict__ tatt,
                     float* __restrict__ out) {
    const int row = blockIdx.x;            // 0..2047
    const int b   = row / NT;
    const int tid = threadIdx.x;

    __shared__ float red[256];
    __shared__ int   redi[256];
    __shared__ float src_acc[NSDV];
    __shared__ float tgt_acc[NTDV];
    __shared__ float sh_max, sh_inv;

    // zero copy accumulators
    for (int i = tid; i < NSDV; i += 256) src_acc[i] = 0.f;
    for (int i = tid; i < NTDV; i += 256) tgt_acc[i] = 0.f;
    __syncthreads();

    // one-hot scatter (copy source / copy target)
    for (int s = tid; s < NS; s += 256)
        atomicAdd(&src_acc[g_src_idx[b*NS + s]], satt[(size_t)row*NS + s]);
    for (int n = tid; n < NT; n += 256)
        atomicAdd(&tgt_acc[g_tgt_idx[b*NT + n]], tatt[(size_t)row*NTDV + n]);

    const float* srow = g_scores + (size_t)row * NV;

    // pass 1: row max (skip masked index 0)
    float m = -INFINITY;
    for (int v = tid; v < NV; v += 256) {
        if (v == 0) continue;
        m = fmaxf(m, srow[v]);
    }
    red[tid] = m;
    __syncthreads();
    for (int o = 128; o > 0; o >>= 1) {
        if (tid < o) red[tid] = fmaxf(red[tid], red[tid + o]);
        __syncthreads();
    }
    if (tid == 0) sh_max = red[0];
    __syncthreads();
    const float rmax = sh_max;

    // pass 2: sum of exp
    float sum = 0.f;
    for (int v = tid; v < NV; v += 256) {
        if (v == 0) continue;
        sum += expf(srow[v] - rmax);
    }
    red[tid] = sum;
    __syncthreads();
    for (int o = 128; o > 0; o >>= 1) {
        if (tid < o) red[tid] += red[tid + o];
        __syncthreads();
    }
    if (tid == 0) sh_inv = 1.0f / red[0];
    __syncthreads();

    const float pg    = g_p[row*3+2];
    const float pcs   = g_p[row*3+0];
    const float pct   = g_p[row*3+1];
    const float scale = pg * sh_inv;

    float*  orow = out + (size_t)row * NOUT;
    float   bmax = -INFINITY;
    int     bidx = 0;

    // pass 3: vocab probs + local argmax
    for (int v = tid; v < NV; v += 256) {
        float pv = (v == 0) ? 0.f : expf(srow[v] - rmax) * scale;
        orow[v] = pv;
        if (pv > bmax) { bmax = pv; bidx = v; }   // v strictly increasing per thread
    }
    // copy-source region
    for (int v = tid; v < NSDV; v += 256) {
        float pv = pcs * src_acc[v];
        orow[NV + v] = pv;
        int gi = NV + v;
        if (pv > bmax || (pv == bmax && gi < bidx)) { bmax = pv; bidx = gi; }
    }
    // copy-target region
    for (int v = tid; v < NTDV; v += 256) {
        float pv = pct * tgt_acc[v];
        orow[NV + NSDV + v] = pv;
        int gi = NV + NSDV + v;
        if (pv > bmax || (pv == bmax && gi < bidx)) { bmax = pv; bidx = gi; }
    }

    // argmax reduce with lowest-index tie-break
    red[tid]  = bmax;
    redi[tid] = bidx;
    __syncthreads();
    for (int o = 128; o > 0; o >>= 1) {
        if (tid < o) {
            float v2 = red[tid + o]; int i2 = redi[tid + o];
            if (v2 > red[tid] || (v2 == red[tid] && i2 < redi[tid])) {
                red[tid] = v2; redi[tid] = i2;
            }
        }
        __syncthreads();
    }
    if (tid == 0)
        out[(size_t)MM * NOUT + row] = (float)redi[0];
}

// ---------------------------------------------------------------------------
extern "C" void kernel_launch(void* const* d_in, const int* in_sizes, int n_in,
                              void* d_out, int out_size) {
    const float* hiddens = (const float*)d_in[0];
    const float* Wp      = (const float*)d_in[1];
    const float* bp      = (const float*)d_in[2];
    const float* Wv      = (const float*)d_in[3];
    const float* bv      = (const float*)d_in[4];
    const float* satt    = (const float*)d_in[5];
    const float* smap    = (const float*)d_in[6];
    const float* tatt    = (const float*)d_in[7];
    const float* tmap    = (const float*)d_in[8];
    float* out = (float*)d_out;

    prep_idx_kernel<<<8, 256>>>(smap, tmap);
    p_kernel<<<MM/4, 128>>>(hiddens, Wp, bp);
    gemm_kernel<<<dim3(NV/128, MM/128), 256>>>(hiddens, Wv, bv);
    finalize_kernel<<<MM, 256>>>(satt, tatt, out);
}

// round 3
// speedup vs baseline: 2.1768x; 2.1768x over previous
#include <cuda_runtime.h>
#include <cuda_bf16.h>
#include <math.h>
#include <stdint.h>

// Problem constants
#define NB   4
#define NT   512
#define NH   512
#define NV   32000
#define NS   512
#define NSDV 300
#define NTDV 512
#define MM   (NB*NT)              // 2048 rows
#define NOUT (NV+NSDV+NTDV)       // 32812
#define KK   (3*NH)               // 1536 expanded K (Ah|Ah|Al x Bh|Bl|Bh)

// Scratch (static device arrays; no allocation allowed)
__device__ float g_scores[(size_t)MM*NV];         // 262 MB
__device__ float g_p[MM*3];
__device__ int   g_src_idx[NB*NS];
__device__ int   g_tgt_idx[NB*NT];
__device__ __nv_bfloat16 g_Ap[(size_t)MM*KK];     // 6.3 MB  [m][k']
__device__ __nv_bfloat16 g_Bp[(size_t)NV*KK];     // 98 MB   [n][k'] (K-major)

// ---------------------------------------------------------------------------
__device__ __forceinline__ uint32_t smem_u32(const void* p) {
    uint32_t a;
    asm("{ .reg .u64 t; cvta.to.shared.u64 t, %1; cvt.u32.u64 %0, t; }"
        : "=r"(a) : "l"(p));
    return a;
}
__device__ __forceinline__ void cp_async16(uint32_t dst, const void* src) {
    asm volatile("cp.async.cg.shared.global [%0], [%1], 16;"
                 :: "r"(dst), "l"(src));
}
#define CP_COMMIT() asm volatile("cp.async.commit_group;")
#define CP_WAIT1()  asm volatile("cp.async.wait_group 1;")

__device__ __forceinline__ void ldmx4(uint32_t* r, uint32_t addr) {
    asm volatile("ldmatrix.sync.aligned.m8n8.x4.shared.b16 {%0,%1,%2,%3}, [%4];"
                 : "=r"(r[0]), "=r"(r[1]), "=r"(r[2]), "=r"(r[3]) : "r"(addr));
}
__device__ __forceinline__ void mma16816(float* c, const uint32_t* a,
                                         const uint32_t* b) {
    asm volatile(
        "mma.sync.aligned.m16n8k16.row.col.f32.bf16.bf16.f32 "
        "{%0,%1,%2,%3}, {%4,%5,%6,%7}, {%8,%9}, {%0,%1,%2,%3};"
        : "+f"(c[0]), "+f"(c[1]), "+f"(c[2]), "+f"(c[3])
        : "r"(a[0]), "r"(a[1]), "r"(a[2]), "r"(a[3]), "r"(b[0]), "r"(b[1]));
}

// ---------------------------------------------------------------------------
// One-hot index extraction
// ---------------------------------------------------------------------------
__global__ void prep_idx_kernel(const float* __restrict__ smap,
                                const float* __restrict__ tmap) {
    int i = blockIdx.x * blockDim.x + threadIdx.x;
    if (i >= NB*NS) return;
    {
        const float* r = smap + (size_t)i * NSDV;
        int idx = 0;
        for (int v = 0; v < NSDV; v++) if (r[v] > 0.5f) idx = v;
        g_src_idx[i] = idx;
    }
    {
        const float* r = tmap + (size_t)i * NTDV;
        int idx = 0;
        for (int v = 0; v < NTDV; v++) if (r[v] > 0.5f) idx = v;
        g_tgt_idx[i] = idx;
    }
}

// ---------------------------------------------------------------------------
// 3-way gate: p = softmax(h @ Wp + bp). One warp per row.
// ---------------------------------------------------------------------------
__global__ void p_kernel(const float* __restrict__ H,
                         const float* __restrict__ Wp,
                         const float* __restrict__ bp) {
    int warp = threadIdx.x >> 5;
    int lane = threadIdx.x & 31;
    int row  = blockIdx.x * 4 + warp;
    if (row >= MM) return;
    const float* h = H + (size_t)row * NH;
    float s0 = 0.f, s1 = 0.f, s2 = 0.f;
    for (int k = lane; k < NH; k += 32) {
        float hv = h[k];
        s0 = fmaf(hv, Wp[k*3+0], s0);
        s1 = fmaf(hv, Wp[k*3+1], s1);
        s2 = fmaf(hv, Wp[k*3+2], s2);
    }
    #pragma unroll
    for (int o = 16; o > 0; o >>= 1) {
        s0 += __shfl_down_sync(0xffffffff, s0, o);
        s1 += __shfl_down_sync(0xffffffff, s1, o);
        s2 += __shfl_down_sync(0xffffffff, s2, o);
    }
    if (lane == 0) {
        s0 += bp[0]; s1 += bp[1]; s2 += bp[2];
        float m = fmaxf(s0, fmaxf(s1, s2));
        float e0 = expf(s0 - m), e1 = expf(s1 - m), e2 = expf(s2 - m);
        float inv = 1.0f / (e0 + e1 + e2);
        g_p[row*3+0] = e0 * inv;
        g_p[row*3+1] = e1 * inv;
        g_p[row*3+2] = e2 * inv;
    }
}

// ---------------------------------------------------------------------------
// Build A' = [Ah | Ah | Al] (bf16) from fp32 hiddens
// ---------------------------------------------------------------------------
__global__ void convA_kernel(const float* __restrict__ A) {
    int i = blockIdx.x * blockDim.x + threadIdx.x;   // MM*NH
    float a = A[i];
    int row = i >> 9, k = i & 511;
    __nv_bfloat16 hi = __float2bfloat16(a);
    __nv_bfloat16 lo = __float2bfloat16(a - __bfloat162float(hi));
    size_t base = (size_t)row * KK + k;
    g_Ap[base]          = hi;
    g_Ap[base + NH]     = hi;
    g_Ap[base + 2*NH]   = lo;
}

// ---------------------------------------------------------------------------
// Transpose Wv [NH][NV] -> B' [NV][K'] = [Bh | Bl | Bh]
// ---------------------------------------------------------------------------
__global__ void convB_kernel(const float* __restrict__ Wv) {
    __shared__ float t[32][33];
    int n0 = blockIdx.x * 32, k0 = blockIdx.y * 32;
    int tx = threadIdx.x, ty = threadIdx.y;   // block (32, 8)
    #pragma unroll
    for (int i = 0; i < 32; i += 8)
        t[ty+i][tx] = Wv[(size_t)(k0 + ty + i) * NV + n0 + tx];   // t[k][n]
    __syncthreads();
    #pragma unroll
    for (int i = 0; i < 32; i += 8) {
        float v = t[tx][ty+i];                 // k = k0+tx, n = n0+ty+i
        __nv_bfloat16 hi = __float2bfloat16(v);
        __nv_bfloat16 lo = __float2bfloat16(v - __bfloat162float(hi));
        size_t base = (size_t)(n0 + ty + i) * KK + k0 + tx;
        g_Bp[base]        = hi;
        g_Bp[base + NH]   = lo;
        g_Bp[base + 2*NH] = hi;
    }
}

// ---------------------------------------------------------------------------
// mma.sync GEMM: g_scores[M][NV] = A' @ B'^T + bias
// 128x128 tiles, BK=64, 3-stage cp.async pipeline, 8 warps of 32x64.
// ---------------------------------------------------------------------------
#define BM 128
#define BN 128
#define BK 64
#define NKITER (KK/BK)        // 24
#define STAGE_B 32768         // A tile 16KB + B tile 16KB
#define SMEM_GEMM (3*STAGE_B) // 96 KB

__global__ __launch_bounds__(256, 1)
void gemm_mma_kernel(const float* __restrict__ bias) {
    extern __shared__ char smem[];
    const uint32_t sb = smem_u32(smem);
    const int tid  = threadIdx.x;
    const int w    = tid >> 5;
    const int lane = tid & 31;
    const int bm   = blockIdx.y * BM;    // 16
    const int bn   = blockIdx.x * BN;    // 250
    const int wm   = w & 3;              // warp row (4)
    const int wn   = w >> 2;             // warp col (2)

    float acc[2][8][4];
    #pragma unroll
    for (int i = 0; i < 2; i++)
        #pragma unroll
        for (int j = 0; j < 8; j++)
            #pragma unroll
            for (int q = 0; q < 4; q++) acc[i][j][q] = 0.f;

    // per-thread load coords: 4 chunks of 16B per tile per stage
    const int lrow = tid >> 3;           // reused: g = tid + i*256 -> row=(g>>3)
    // stage loader
    auto dummy = 0; (void)dummy;

#define LOAD_STAGE(kt, s) do {                                                  \
    uint32_t base = sb + (uint32_t)(s) * STAGE_B;                               \
    int k0 = (kt) * BK;                                                         \
    _Pragma("unroll")                                                           \
    for (int i = 0; i < 4; i++) {                                               \
        int g   = tid + i * 256;                                                \
        int row = g >> 3, c = g & 7;                                            \
        uint32_t sw = (uint32_t)row * 128 + (uint32_t)((c ^ (row & 7)) * 16);   \
        cp_async16(base + sw,                                                   \
                   g_Ap + (size_t)(bm + row) * KK + k0 + c * 8);                \
        cp_async16(base + 16384 + sw,                                           \
                   g_Bp + (size_t)(bn + row) * KK + k0 + c * 8);                \
    }                                                                           \
    CP_COMMIT();                                                                \
} while (0)

    LOAD_STAGE(0, 0);
    LOAD_STAGE(1, 1);

    for (int kt = 0; kt < NKITER; kt++) {
        const int s = kt % 3;
        CP_WAIT1();
        __syncthreads();
        if (kt + 2 < NKITER) LOAD_STAGE(kt + 2, (kt + 2) % 3);

        const uint32_t abase = sb + (uint32_t)s * STAGE_B;
        const uint32_t bbase = abase + 16384;
        #pragma unroll
        for (int ks = 0; ks < 4; ks++) {
            uint32_t a[2][4];
            #pragma unroll
            for (int i = 0; i < 2; i++) {
                int row = wm * 32 + i * 16 + (lane & 15);
                int ch  = ks * 2 + (lane >> 4);
                uint32_t addr = abase + (uint32_t)row * 128
                              + (uint32_t)((ch ^ (row & 7)) * 16);
                ldmx4(a[i], addr);
            }
            uint32_t b[8][2];
            #pragma unroll
            for (int jj = 0; jj < 4; jj++) {
                int row = wn * 64 + jj * 16 + (lane & 15);
                int ch  = ks * 2 + (lane >> 4);
                uint32_t addr = bbase + (uint32_t)row * 128
                              + (uint32_t)((ch ^ (row & 7)) * 16);
                uint32_t r[4];
                ldmx4(r, addr);
                b[2*jj][0]   = r[0]; b[2*jj][1]   = r[2];
                b[2*jj+1][0] = r[1]; b[2*jj+1][1] = r[3];
            }
            #pragma unroll
            for (int i = 0; i < 2; i++)
                #pragma unroll
                for (int j = 0; j < 8; j++)
                    mma16816(acc[i][j], a[i], b[j]);
        }
    }
    (void)lrow;

    // epilogue: bias add + store
    #pragma unroll
    for (int i = 0; i < 2; i++) {
        #pragma unroll
        for (int j = 0; j < 8; j++) {
            int row = bm + wm * 32 + i * 16 + (lane >> 2);
            int col = bn + wn * 64 + j * 8 + (lane & 3) * 2;
            float b0 = bias[col], b1 = bias[col + 1];
            float2 v0 = make_float2(acc[i][j][0] + b0, acc[i][j][1] + b1);
            float2 v1 = make_float2(acc[i][j][2] + b0, acc[i][j][3] + b1);
            *(float2*)(g_scores + (size_t)row * NV + col)       = v0;
            *(float2*)(g_scores + (size_t)(row + 8) * NV + col) = v1;
        }
    }
}

// ---------------------------------------------------------------------------
// Per-row: online softmax over V (index 0 masked), scale by p_generate,
// one-hot copy scatters, concat write, fused argmax.
// ---------------------------------------------------------------------------
__global__ __launch_bounds__(256)
void finalize_kernel(const float* __restrict__ satt,
                     const float* __restrict__ tatt,
                     float* __restrict__ out) {
    const int row = blockIdx.x;
    const int b   = row / NT;
    const int tid = threadIdx.x;

    __shared__ float red[256];
    __shared__ float redS[256];
    __shared__ int   redi[256];
    __shared__ float src_acc[NSDV];
    __shared__ float tgt_acc[NTDV];
    __shared__ float sh_max, sh_inv;

    for (int i = tid; i < NSDV; i += 256) src_acc[i] = 0.f;
    for (int i = tid; i < NTDV; i += 256) tgt_acc[i] = 0.f;
    __syncthreads();

    for (int s = tid; s < NS; s += 256)
        atomicAdd(&src_acc[g_src_idx[b*NS + s]], satt[(size_t)row*NS + s]);
    for (int n = tid; n < NT; n += 256)
        atomicAdd(&tgt_acc[g_tgt_idx[b*NT + n]], tatt[(size_t)row*NTDV + n]);

    const float4* srow4 = (const float4*)(g_scores + (size_t)row * NV);

    // pass 1: online max+sum (single read)
    float m = -INFINITY, s = 0.f;
    for (int i = tid; i < NV/4; i += 256) {
        float4 v = srow4[i];
        if (i == 0) v.x = -INFINITY;   // masked index 0
        float lm = fmaxf(fmaxf(v.x, v.y), fmaxf(v.z, v.w));
        if (lm > m) { s *= expf(m - lm); m = lm; }
        s += expf(v.x - m) + expf(v.y - m) + expf(v.z - m) + expf(v.w - m);
    }
    red[tid] = m; redS[tid] = s;
    __syncthreads();
    for (int o = 128; o > 0; o >>= 1) {
        if (tid < o) {
            float m2 = red[tid+o], s2 = redS[tid+o];
            float M = fmaxf(red[tid], m2);
            redS[tid] = redS[tid]*expf(red[tid]-M) + s2*expf(m2-M);
            red[tid]  = M;
        }
        __syncthreads();
    }
    if (tid == 0) { sh_max = red[0]; sh_inv = 1.0f / redS[0]; }
    __syncthreads();
    const float rmax = sh_max;

    const float pg    = g_p[row*3+2];
    const float pcs   = g_p[row*3+0];
    const float pct   = g_p[row*3+1];
    const float scale = pg * sh_inv;

    float* orow = out + (size_t)row * NOUT;
    float4* orow4 = (float4*)orow;
    float   bmax = -INFINITY;
    int     bidx = 0;

    for (int i = tid; i < NV/4; i += 256) {
        float4 v = srow4[i];
        float4 p;
        p.x = expf(v.x - rmax) * scale;
        p.y = expf(v.y - rmax) * scale;
        p.z = expf(v.z - rmax) * scale;
        p.w = expf(v.w - rmax) * scale;
        if (i == 0) p.x = 0.f;
        orow4[i] = p;
        int base = i * 4;
        if (p.x > bmax) { bmax = p.x; bidx = base;   }
        if (p.y > bmax) { bmax = p.y; bidx = base+1; }
        if (p.z > bmax) { bmax = p.z; bidx = base+2; }
        if (p.w > bmax) { bmax = p.w; bidx = base+3; }
    }
    for (int v = tid; v < NSDV; v += 256) {
        float pv = pcs * src_acc[v];
        orow[NV + v] = pv;
        int gi = NV + v;
        if (pv > bmax || (pv == bmax && gi < bidx)) { bmax = pv; bidx = gi; }
    }
    for (int v = tid; v < NTDV; v += 256) {
        float pv = pct * tgt_acc[v];
        orow[NV + NSDV + v] = pv;
        int gi = NV + NSDV + v;
        if (pv > bmax || (pv == bmax && gi < bidx)) { bmax = pv; bidx = gi; }
    }

    red[tid]  = bmax;
    redi[tid] = bidx;
    __syncthreads();
    for (int o = 128; o > 0; o >>= 1) {
        if (tid < o) {
            float v2 = red[tid + o]; int i2 = redi[tid + o];
            if (v2 > red[tid] || (v2 == red[tid] && i2 < redi[tid])) {
                red[tid] = v2; redi[tid] = i2;
            }
        }
        __syncthreads();
    }
    if (tid == 0)
        out[(size_t)MM * NOUT + row] = (float)redi[0];
}

// ---------------------------------------------------------------------------
extern "C" void kernel_launch(void* const* d_in, const int* in_sizes, int n_in,
                              void* d_out, int out_size) {
    const float* hiddens = (const float*)d_in[0];
    const float* Wp      = (const float*)d_in[1];
    const float* bp      = (const float*)d_in[2];
    const float* Wv      = (const float*)d_in[3];
    const float* bv      = (const float*)d_in[4];
    const float* satt    = (const float*)d_in[5];
    const float* smap    = (const float*)d_in[6];
    const float* tatt    = (const float*)d_in[7];
    const float* tmap    = (const float*)d_in[8];
    float* out = (float*)d_out;

    cudaFuncSetAttribute(gemm_mma_kernel,
                         cudaFuncAttributeMaxDynamicSharedMemorySize, SMEM_GEMM);

    prep_idx_kernel<<<8, 256>>>(smap, tmap);
    p_kernel<<<MM/4, 128>>>(hiddens, Wp, bp);
    convA_kernel<<<(MM*NH)/256, 256>>>(hiddens);
    convB_kernel<<<dim3(NV/32, NH/32), dim3(32, 8)>>>(Wv);
    gemm_mma_kernel<<<dim3(NV/BN, MM/BM), 256, SMEM_GEMM>>>(bv);
    finalize_kernel<<<MM, 256>>>(satt, tatt, out);
}